// round 4
// baseline (speedup 1.0000x reference)
#include <cuda_runtime.h>
#include <math.h>

#define Bq 2
#define Lq 5
#define Nq 10
#define Cq 64
#define Hq 128
#define Wq 256
#define HWq (Hq * Wq)          // 32768
#define NHWq (Nq * HWq)        // 327680
#define OUTQ (Bq * Cq * HWq)   // 4194304

#define MGX (Wq / 64)          // 4
#define MGY (Hq / 4)           // 32
#define MASK_BLOCKS (MGX * MGY * Nq)   // 1280

// ---------------- scratch (no allocations allowed) ----------------
__device__ float        g_mask[NHWq];
__device__ float        g_sum[Bq * Cq];
__device__ unsigned int g_maxu[Bq * Cq];    // monotonic-encoded float max
__device__ int          g_blkcnt[MASK_BLOCKS];

// 5x5 Gaussian, sigma=1: 1/(2*pi*sigma) * exp(-(dx^2+dy^2)/2)  (NOT normalized, matches ref)
__constant__ float GK[25] = {
    0.0029150243f, 0.0130642333f, 0.0215392793f, 0.0130642333f, 0.0029150243f,
    0.0130642333f, 0.0585498315f, 0.0965323526f, 0.0585498315f, 0.0130642333f,
    0.0215392793f, 0.0965323526f, 0.1591549431f, 0.0965323526f, 0.0215392793f,
    0.0130642333f, 0.0585498315f, 0.0965323526f, 0.0585498315f, 0.0130642333f,
    0.0029150243f, 0.0130642333f, 0.0215392793f, 0.0130642333f, 0.0029150243f
};

// fast sigmoid (MUFU path); feeds threshold/softmax, precision ample
__device__ __forceinline__ float fsig(float x) { return 1.0f / (1.0f + __expf(-x)); }

// monotonic float<->uint order-preserving encode (max identity = 0u)
__device__ __forceinline__ unsigned int fenc(float f) {
    unsigned int u = __float_as_uint(f);
    return (u & 0x80000000u) ? ~u : (u | 0x80000000u);
}
__device__ __forceinline__ float fdec(unsigned int e) {
    return __uint_as_float((e & 0x80000000u) ? (e & 0x7FFFFFFFu) : ~e);
}

// ============ kernel 1: conf (sigmoid/max/AoI) + gaussian + mask, fused via smem halo ============
__global__ void __launch_bounds__(256) conf_mask_kernel(
        const float* __restrict__ psm,
        const float* __restrict__ inv_delay,
        const float* __restrict__ ewc_w,
        const float* __restrict__ ewc_b) {
    const int TX = 64, TY = 4;
    __shared__ float sc[TY + 4][TX + 4];   // 8 x 68 tile with 2-halo
    __shared__ int s_cnt;

    int n  = blockIdx.z;
    int w0 = blockIdx.x * TX;
    int h0 = blockIdx.y * TY;
    int tid = threadIdx.x;

    // re-init pooling scratch each replay (stream-ordered before fuse's atomics)
    if (blockIdx.x == 0 && blockIdx.y == 0 && n == 0 && tid < Bq * Cq) {
        g_sum[tid]  = 0.0f;
        g_maxu[tid] = 0u;                 // encodes below any real float
    }
    if (tid == 0) s_cnt = 0;

    float enc = tanhf(inv_delay[n] * ewc_w[0] + ewc_b[0]) + 1.0f;
    const float* p0 = psm + (size_t)(n * 2 + 0) * HWq;
    const float* p1 = psm + (size_t)(n * 2 + 1) * HWq;

#pragma unroll
    for (int k = 0; k < 3; k++) {
        int i = tid + k * 256;
        if (i < (TY + 4) * (TX + 4)) {
            int sy = i / (TX + 4);
            int sx = i - sy * (TX + 4);
            int h = h0 + sy - 2, w = w0 + sx - 2;
            float v = 0.0f;                               // zero-pad = 'SAME'
            if (h >= 0 && h < Hq && w >= 0 && w < Wq) {
                int idx = h * Wq + w;
                v = fmaxf(fsig(p0[idx]), fsig(p1[idx])) * enc;
            }
            sc[sy][sx] = v;
        }
    }
    __syncthreads();

    int tx = tid & 63, ty = tid >> 6;
    float acc = 0.0f;
#pragma unroll
    for (int dy = 0; dy < 5; dy++)
#pragma unroll
        for (int dx = 0; dx < 5; dx++)
            acc += GK[dy * 5 + dx] * sc[ty + dy][tx + dx];

    float m = (acc > 0.01f) ? 1.0f : 0.0f;
    if (n % Lq == 0) m = 1.0f;                            // ego always communicates
    g_mask[(size_t)n * HWq + (h0 + ty) * Wq + (w0 + tx)] = m;

    unsigned bal = __ballot_sync(0xffffffffu, m > 0.5f);
    if ((tid & 31) == 0) atomicAdd(&s_cnt, __popc(bal));
    __syncthreads();
    if (tid == 0)
        g_blkcnt[(n * MGY + blockIdx.y) * MGX + blockIdx.x] = s_cnt;
}

// ============ kernel 2: single-pass per-pixel cross-agent attention + pooling ============
// block = 256 threads = 8 warps; warp w owns channels [8w, 8w+8) for 32 pixels.
// x values held in registers across dot-product and output phases: x read ONCE from DRAM.
// Pool updates are hardware REDs (no CAS loops, no return values).
__global__ void __launch_bounds__(256) fuse_kernel(
        const float* __restrict__ x,
        const float* __restrict__ inv_delay,
        const float* __restrict__ ew_w,
        const float* __restrict__ ew_b,
        float* __restrict__ out) {
    __shared__ float s_part[8][Lq][32];
    __shared__ float s_enw[Lq];

    int b    = blockIdx.y;
    int lane = threadIdx.x & 31;
    int wid  = threadIdx.x >> 5;
    int p    = blockIdx.x * 32 + lane;

    if (threadIdx.x < Lq)
        s_enw[threadIdx.x] = tanhf(inv_delay[b * Lq + threadIdx.x] * ew_w[0] + ew_b[0]) + 1.0f;

    float mk[Lq];
#pragma unroll
    for (int l = 0; l < Lq; l++) mk[l] = g_mask[(size_t)(b * Lq + l) * HWq + p];

    // registers: 8 channels x 5 agents
    const float* xb = x + ((size_t)(b * Lq) * Cq + wid * 8) * HWq + p;
    float xv[8][Lq];
#pragma unroll
    for (int c = 0; c < 8; c++)
#pragma unroll
        for (int l = 0; l < Lq; l++)
            xv[c][l] = xb[((size_t)l * Cq + c) * HWq];

    // partial dots (ego . feat_l over this warp's channels)
    float pd[Lq] = {0.f, 0.f, 0.f, 0.f, 0.f};
#pragma unroll
    for (int c = 0; c < 8; c++) {
        float e = xv[c][0];
#pragma unroll
        for (int l = 0; l < Lq; l++) pd[l] += e * xv[c][l];
    }
#pragma unroll
    for (int l = 0; l < Lq; l++) s_part[wid][l][lane] = pd[l];
    __syncthreads();

    float dot[Lq];
#pragma unroll
    for (int l = 0; l < Lq; l++) {
        float t = 0.0f;
#pragma unroll
        for (int w = 0; w < 8; w++) t += s_part[w][l][lane];
        dot[l] = t;
    }

    // masked AoI scales folded into scores (masked feats are zeros in ref's softmax)
    float s[Lq];
#pragma unroll
    for (int l = 0; l < Lq; l++) s[l] = s_enw[l] * mk[l];

    float scv[Lq], mx = -INFINITY;
#pragma unroll
    for (int l = 0; l < Lq; l++) {
        scv[l] = dot[l] * s[0] * s[l] * 0.125f;           // 1/sqrt(64)
        mx = fmaxf(mx, scv[l]);
    }
    float esum = 0.0f;
#pragma unroll
    for (int l = 0; l < Lq; l++) { scv[l] = __expf(scv[l] - mx); esum += scv[l]; }
    float inv = 1.0f / esum;
    float coef[Lq];
#pragma unroll
    for (int l = 0; l < Lq; l++) coef[l] = scv[l] * inv * s[l];

    // output from registers + per-channel pooling (warp owns channel -> warp reduce)
    float* ob = out + ((size_t)b * Cq + wid * 8) * HWq + p;
    int cbase = b * Cq + wid * 8;
#pragma unroll
    for (int c = 0; c < 8; c++) {
        float f = 0.0f;
#pragma unroll
        for (int l = 0; l < Lq; l++) f += coef[l] * xv[c][l];
        ob[(size_t)c * HWq] = f;
        float ws = f, wm = f;
#pragma unroll
        for (int o = 16; o > 0; o >>= 1) {
            ws += __shfl_xor_sync(0xffffffffu, ws, o);
            wm = fmaxf(wm, __shfl_xor_sync(0xffffffffu, wm, o));
        }
        if (lane == 0) {
            atomicAdd(&g_sum[cbase + c], ws);             // RED.ADD (no return)
            atomicMax(&g_maxu[cbase + c], fenc(wm));      // RED.MAX.U32 (no CAS loop)
        }
    }
}

// ============ kernel 3: gate MLP (per block, warp-coop) + apply + comm_rate ============
// Each block covers 1024 consecutive floats of out = exactly one (b,c) channel slice.
__global__ void __launch_bounds__(256) scale_gate_kernel(
        const float* __restrict__ w1,   // (4,64)
        const float* __restrict__ w2,   // (64,4)
        float* __restrict__ out, int out_size) {
    __shared__ float s_gate;
    __shared__ int s_red[256];

    int tid = threadIdx.x;
    int cg = (blockIdx.x * 1024) / HWq;   // 0..127 = b*64+c
    int b = cg >> 6, c = cg & 63;

    if (tid < 32) {
        float pa[4] = {0, 0, 0, 0}, pm[4] = {0, 0, 0, 0};
#pragma unroll
        for (int k = 0; k < 2; k++) {
            int cc = tid + k * 32;
            float av = g_sum[b * Cq + cc] * (1.0f / HWq);
            float mv = fdec(g_maxu[b * Cq + cc]);
#pragma unroll
            for (int j = 0; j < 4; j++) {
                float w = w1[j * Cq + cc];
                pa[j] += av * w;
                pm[j] += mv * w;
            }
        }
#pragma unroll
        for (int o = 16; o > 0; o >>= 1) {
#pragma unroll
            for (int j = 0; j < 4; j++) {
                pa[j] += __shfl_xor_sync(0xffffffffu, pa[j], o);
                pm[j] += __shfl_xor_sync(0xffffffffu, pm[j], o);
            }
        }
        if (tid == 0) {
            float og = 0.0f;
#pragma unroll
            for (int j = 0; j < 4; j++)
                og += (fmaxf(pa[j], 0.0f) + fmaxf(pm[j], 0.0f)) * w2[c * 4 + j];
            s_gate = 1.0f / (1.0f + expf(-og));
        }
    }
    if (blockIdx.x == 0) {
        int t = 0;
        for (int i = tid; i < MASK_BLOCKS; i += 256) t += g_blkcnt[i];
        s_red[tid] = t;
    }
    __syncthreads();

    float g = s_gate;
    float4* o4 = (float4*)out + (size_t)blockIdx.x * 256 + tid;
    float4 v = *o4;
    v.x *= g; v.y *= g; v.z *= g; v.w *= g;
    *o4 = v;

    if (blockIdx.x == 0) {
        for (int st = 128; st > 0; st >>= 1) {
            __syncthreads();
            if (tid < st) s_red[tid] += s_red[tid + st];
        }
        if (tid == 0 && out_size > OUTQ)
            out[OUTQ] = (float)s_red[0] / (float)NHWq;
    }
}

// ---------------- launch ----------------
extern "C" void kernel_launch(void* const* d_in, const int* in_sizes, int n_in,
                              void* d_out, int out_size) {
    const float* x         = (const float*)d_in[0];
    const float* psm       = (const float*)d_in[1];
    const float* inv_delay = (const float*)d_in[2];
    const float* ew_w      = (const float*)d_in[3];
    const float* ew_b      = (const float*)d_in[4];
    const float* ewc_w     = (const float*)d_in[5];
    const float* ewc_b     = (const float*)d_in[6];
    const float* sta_w1    = (const float*)d_in[7];
    const float* sta_w2    = (const float*)d_in[8];
    float* out = (float*)d_out;

    dim3 gm(MGX, MGY, Nq);
    conf_mask_kernel<<<gm, 256>>>(psm, inv_delay, ewc_w, ewc_b);
    dim3 gf(HWq / 32, Bq);
    fuse_kernel<<<gf, 256>>>(x, inv_delay, ew_w, ew_b, out);
    scale_gate_kernel<<<OUTQ / 1024, 256>>>(sta_w1, sta_w2, out, out_size);
}

// round 6
// speedup vs baseline: 3.2364x; 3.2364x over previous
#include <cuda_runtime.h>
#include <math.h>

#define Bq 2
#define Lq 5
#define Nq 10
#define Cq 64
#define Hq 128
#define Wq 256
#define HWq (Hq * Wq)          // 32768
#define NHWq (Nq * HWq)        // 327680
#define OUTQ (Bq * Cq * HWq)   // 4194304

#define MGX (Wq / 64)          // 4
#define MGY (Hq / 4)           // 32
#define MASK_BLOCKS (MGX * MGY * Nq)   // 1280

#define NSLOT 64               // pooling replication factor (decontends L2 atomics)

// ---------------- scratch (no allocations allowed) ----------------
__device__ float        g_mask[NHWq];
__device__ float        g_sum_r[NSLOT][Bq * Cq];
__device__ unsigned int g_max_r[NSLOT][Bq * Cq];   // monotonic-encoded float max
__device__ float        g_gate[Bq * Cq];
__device__ int          g_blkcnt[MASK_BLOCKS];

// separable 5-tap Gaussian, sigma=1:  k2d = (1/2pi) * g1[dy] * g1[dx],  g1 = exp(-d^2/2)
__constant__ float GX[5] = {0.13533528f, 0.60653066f, 1.0f, 0.60653066f, 0.13533528f};
__constant__ float GY[5] = {0.13533528f * 0.15915494f, 0.60653066f * 0.15915494f,
                            0.15915494f, 0.60653066f * 0.15915494f, 0.13533528f * 0.15915494f};

__device__ __forceinline__ float fsig(float x) { return 1.0f / (1.0f + __expf(-x)); }

// monotonic float<->uint order-preserving encode (max identity = 0u)
__device__ __forceinline__ unsigned int fenc(float f) {
    unsigned int u = __float_as_uint(f);
    return (u & 0x80000000u) ? ~u : (u | 0x80000000u);
}
__device__ __forceinline__ float fdec(unsigned int e) {
    return __uint_as_float((e & 0x80000000u) ? (e & 0x7FFFFFFFu) : ~e);
}

// ============ kernel 1: conf + SEPARABLE gaussian + mask (smem halo, 2-stage) ============
__global__ void __launch_bounds__(256) conf_mask_kernel(
        const float* __restrict__ psm,
        const float* __restrict__ inv_delay,
        const float* __restrict__ ewc_w,
        const float* __restrict__ ewc_b) {
    const int TX = 64, TY = 4;
    __shared__ float sc[TY + 4][TX + 4];   // conf with 2-halo (8 x 68)
    __shared__ float ht[TY + 4][TX];       // horizontal-filtered (8 x 64)
    __shared__ int s_cnt;

    int n  = blockIdx.z;
    int w0 = blockIdx.x * TX;
    int h0 = blockIdx.y * TY;
    int tid = threadIdx.x;
    int flat = (n * MGY + blockIdx.y) * MGX + blockIdx.x;

    // re-init replicated pooling scratch each replay (first NSLOT blocks; stream-ordered)
    if (flat < NSLOT) {
        if (tid < Bq * Cq)            g_sum_r[flat][tid] = 0.0f;
        else if (tid < 2 * Bq * Cq)   g_max_r[flat][tid - Bq * Cq] = 0u;
    }
    if (tid == 0) s_cnt = 0;

    float enc = tanhf(inv_delay[n] * ewc_w[0] + ewc_b[0]) + 1.0f;
    const float* p0 = psm + (size_t)(n * 2 + 0) * HWq;
    const float* p1 = psm + (size_t)(n * 2 + 1) * HWq;

    // stage 1: conf tile with halo (544 elements, 256 threads)
#pragma unroll
    for (int k = 0; k < 3; k++) {
        int i = tid + k * 256;
        if (i < (TY + 4) * (TX + 4)) {
            int sy = i / (TX + 4);
            int sx = i - sy * (TX + 4);
            int h = h0 + sy - 2, w = w0 + sx - 2;
            float v = 0.0f;                               // zero-pad = 'SAME'
            if (h >= 0 && h < Hq && w >= 0 && w < Wq) {
                int idx = h * Wq + w;
                v = fmaxf(fsig(p0[idx]), fsig(p1[idx])) * enc;
            }
            sc[sy][sx] = v;
        }
    }
    __syncthreads();

    // stage 2: horizontal 5-tap (512 elements, 2 per thread)
#pragma unroll
    for (int k = 0; k < 2; k++) {
        int i = tid + k * 256;          // i = sy*64 + sx
        int sy = i >> 6, sx = i & 63;
        float a = 0.0f;
#pragma unroll
        for (int d = 0; d < 5; d++) a += GX[d] * sc[sy][sx + d];
        ht[sy][sx] = a;
    }
    __syncthreads();

    // stage 3: vertical 5-tap + threshold + ego + count
    int tx = tid & 63, ty = tid >> 6;
    float acc = 0.0f;
#pragma unroll
    for (int d = 0; d < 5; d++) acc += GY[d] * ht[ty + d][tx];

    float m = (acc > 0.01f) ? 1.0f : 0.0f;
    if (n % Lq == 0) m = 1.0f;                            // ego always communicates
    g_mask[(size_t)n * HWq + (h0 + ty) * Wq + (w0 + tx)] = m;

    unsigned bal = __ballot_sync(0xffffffffu, m > 0.5f);
    if ((tid & 31) == 0) atomicAdd(&s_cnt, __popc(bal));
    __syncthreads();
    if (tid == 0) g_blkcnt[flat] = s_cnt;
}

// ============ kernel 2: single-pass per-pixel cross-agent attention + pooling ============
// 8 warps; warp w owns channels [8w, 8w+8) for 32 pixels. x read ONCE from DRAM.
// Pool REDs go to NSLOT-replicated accumulators -> no L2-slice serialization.
__global__ void __launch_bounds__(256) fuse_kernel(
        const float* __restrict__ x,
        const float* __restrict__ inv_delay,
        const float* __restrict__ ew_w,
        const float* __restrict__ ew_b,
        float* __restrict__ out) {
    __shared__ float s_part[8][Lq][32];
    __shared__ float s_enw[Lq];

    int b    = blockIdx.y;
    int lane = threadIdx.x & 31;
    int wid  = threadIdx.x >> 5;
    int p    = blockIdx.x * 32 + lane;
    int slot = blockIdx.x & (NSLOT - 1);

    if (threadIdx.x < Lq)
        s_enw[threadIdx.x] = tanhf(inv_delay[b * Lq + threadIdx.x] * ew_w[0] + ew_b[0]) + 1.0f;

    float mk[Lq];
#pragma unroll
    for (int l = 0; l < Lq; l++) mk[l] = g_mask[(size_t)(b * Lq + l) * HWq + p];

    const float* xb = x + ((size_t)(b * Lq) * Cq + wid * 8) * HWq + p;
    float xv[8][Lq];
#pragma unroll
    for (int c = 0; c < 8; c++)
#pragma unroll
        for (int l = 0; l < Lq; l++)
            xv[c][l] = xb[((size_t)l * Cq + c) * HWq];

    float pd[Lq] = {0.f, 0.f, 0.f, 0.f, 0.f};
#pragma unroll
    for (int c = 0; c < 8; c++) {
        float e = xv[c][0];
#pragma unroll
        for (int l = 0; l < Lq; l++) pd[l] += e * xv[c][l];
    }
#pragma unroll
    for (int l = 0; l < Lq; l++) s_part[wid][l][lane] = pd[l];
    __syncthreads();

    float dot[Lq];
#pragma unroll
    for (int l = 0; l < Lq; l++) {
        float t = 0.0f;
#pragma unroll
        for (int w = 0; w < 8; w++) t += s_part[w][l][lane];
        dot[l] = t;
    }

    float s[Lq];
#pragma unroll
    for (int l = 0; l < Lq; l++) s[l] = s_enw[l] * mk[l];

    float scv[Lq], mx = -INFINITY;
#pragma unroll
    for (int l = 0; l < Lq; l++) {
        scv[l] = dot[l] * s[0] * s[l] * 0.125f;           // 1/sqrt(64)
        mx = fmaxf(mx, scv[l]);
    }
    float esum = 0.0f;
#pragma unroll
    for (int l = 0; l < Lq; l++) { scv[l] = __expf(scv[l] - mx); esum += scv[l]; }
    float inv = 1.0f / esum;
    float coef[Lq];
#pragma unroll
    for (int l = 0; l < Lq; l++) coef[l] = scv[l] * inv * s[l];

    float* ob = out + ((size_t)b * Cq + wid * 8) * HWq + p;
    int cbase = b * Cq + wid * 8;
#pragma unroll
    for (int c = 0; c < 8; c++) {
        float f = 0.0f;
#pragma unroll
        for (int l = 0; l < Lq; l++) f += coef[l] * xv[c][l];
        ob[(size_t)c * HWq] = f;
        float ws = f, wm = f;
#pragma unroll
        for (int o = 16; o > 0; o >>= 1) {
            ws += __shfl_xor_sync(0xffffffffu, ws, o);
            wm = fmaxf(wm, __shfl_xor_sync(0xffffffffu, wm, o));
        }
        if (lane == 0) {
            atomicAdd(&g_sum_r[slot][cbase + c], ws);         // decontended RED.ADD
            atomicMax(&g_max_r[slot][cbase + c], fenc(wm));   // decontended RED.MAX.U32
        }
    }
}

// ============ kernel 3: fold slots + gate MLP + comm_rate (single small block) ============
__global__ void __launch_bounds__(256) reduce_gate_kernel(
        const float* __restrict__ w1,   // (4,64)
        const float* __restrict__ w2,   // (64,4)
        float* __restrict__ out, int out_size) {
    __shared__ float s_avg[Bq * Cq];
    __shared__ float s_mx[Bq * Cq];
    __shared__ int s_red[256];

    int tid = threadIdx.x;

    if (tid < Bq * Cq) {
        float a = 0.0f;
#pragma unroll 8
        for (int s = 0; s < NSLOT; s++) a += g_sum_r[s][tid];
        s_avg[tid] = a * (1.0f / HWq);
    } else {
        int c = tid - Bq * Cq;
        unsigned int e = 0u;
#pragma unroll 8
        for (int s = 0; s < NSLOT; s++) e = max(e, g_max_r[s][c]);
        s_mx[c] = fdec(e);
    }

    int t = 0;
    for (int i = tid; i < MASK_BLOCKS; i += 256) t += g_blkcnt[i];
    s_red[tid] = t;
    __syncthreads();

    if (tid < Bq * Cq) {
        int b = tid >> 6, c = tid & 63;
        float og = 0.0f;
#pragma unroll
        for (int j = 0; j < 4; j++) {
            float sa = 0.0f, sm = 0.0f;
            for (int cc = 0; cc < Cq; cc++) {
                float w = w1[j * Cq + cc];
                sa += s_avg[b * Cq + cc] * w;
                sm += s_mx[b * Cq + cc] * w;
            }
            og += (fmaxf(sa, 0.0f) + fmaxf(sm, 0.0f)) * w2[c * 4 + j];
        }
        g_gate[tid] = 1.0f / (1.0f + expf(-og));
    }

    for (int st = 128; st > 0; st >>= 1) {
        __syncthreads();
        if (tid < st) s_red[tid] += s_red[tid + st];
    }
    if (tid == 0 && out_size > OUTQ)
        out[OUTQ] = (float)s_red[0] / (float)NHWq;
}

// ============ kernel 4: pure streaming gate apply ============
__global__ void __launch_bounds__(256) scale_kernel(float* __restrict__ out) {
    int cg = blockIdx.x >> 5;             // 1024 floats per block, HWq/1024=32 blocks per channel
    float g = g_gate[cg];
    float4* o4 = (float4*)out + (size_t)blockIdx.x * 256 + threadIdx.x;
    float4 v = *o4;
    v.x *= g; v.y *= g; v.z *= g; v.w *= g;
    *o4 = v;
}

// ---------------- launch ----------------
extern "C" void kernel_launch(void* const* d_in, const int* in_sizes, int n_in,
                              void* d_out, int out_size) {
    const float* x         = (const float*)d_in[0];
    const float* psm       = (const float*)d_in[1];
    const float* inv_delay = (const float*)d_in[2];
    const float* ew_w      = (const float*)d_in[3];
    const float* ew_b      = (const float*)d_in[4];
    const float* ewc_w     = (const float*)d_in[5];
    const float* ewc_b     = (const float*)d_in[6];
    const float* sta_w1    = (const float*)d_in[7];
    const float* sta_w2    = (const float*)d_in[8];
    float* out = (float*)d_out;

    dim3 gm(MGX, MGY, Nq);
    conf_mask_kernel<<<gm, 256>>>(psm, inv_delay, ewc_w, ewc_b);
    dim3 gf(HWq / 32, Bq);
    fuse_kernel<<<gf, 256>>>(x, inv_delay, ew_w, ew_b, out);
    reduce_gate_kernel<<<1, 256>>>(sta_w1, sta_w2, out, out_size);
    scale_kernel<<<OUTQ / 1024, 256>>>(out);
}